// round 5
// baseline (speedup 1.0000x reference)
#include <cuda_runtime.h>

// Problem constants
#define NNODES   100000
#define NEDGES   30000
#define NPAIRS   1600000
#define DFEAT    64
#define NEG_SLOPE 0.2f

// Scratch (device globals: allocation-free)
__device__ int   g_hist_e[NEDGES];
__device__ int   g_off_e [NEDGES + 1];
__device__ int   g_cur_e [NEDGES];
__device__ int   g_hist_v[NNODES];
__device__ int   g_off_v [NNODES + 1];
__device__ int   g_cur_v [NNODES];
__device__ int   g_mem_e [NPAIRS];      // vertex ids grouped by edge
__device__ int   g_mem_v [NPAIRS];      // edge ids grouped by vertex
__device__ float g_A  [NEDGES * DFEAT]; // per-edge input-space accumulators
__device__ float g_sd [NEDGES];         // per-edge sum(degV)
__device__ float g_Xe [NEDGES * DFEAT]; // per-edge output features

// ---------------------------------------------------------------------------
// K_init: zero histograms
// ---------------------------------------------------------------------------
__global__ __launch_bounds__(256) void k_init()
{
    int stride = gridDim.x * blockDim.x;
    for (int i = blockIdx.x * blockDim.x + threadIdx.x; i < NNODES; i += stride) {
        g_hist_v[i] = 0;
        if (i < NEDGES) g_hist_e[i] = 0;
    }
}

// ---------------------------------------------------------------------------
// K_hist: count members per edge and per vertex
// ---------------------------------------------------------------------------
__global__ __launch_bounds__(256) void k_hist(
    const int* __restrict__ vertex, const int* __restrict__ edges, int n)
{
    int stride = gridDim.x * blockDim.x;
    for (int i = blockIdx.x * blockDim.x + threadIdx.x; i < n; i += stride) {
        atomicAdd(&g_hist_e[edges[i]], 1);
        atomicAdd(&g_hist_v[vertex[i]], 1);
    }
}

// ---------------------------------------------------------------------------
// K_scan: exclusive prefix sum (block 0 -> edge hist, block 1 -> vertex hist)
// warp-shuffle scan, sequential 1024-chunks with carry
// ---------------------------------------------------------------------------
__global__ __launch_bounds__(1024) void k_scan()
{
    const int* h; int* off; int* cur; int n;
    if (blockIdx.x == 0) { h = g_hist_e; off = g_off_e; cur = g_cur_e; n = NEDGES; }
    else                 { h = g_hist_v; off = g_off_v; cur = g_cur_v; n = NNODES; }

    __shared__ int wsum[32];
    __shared__ int carry;
    int t = threadIdx.x, lane = t & 31, w = t >> 5;
    if (t == 0) carry = 0;
    __syncthreads();

    for (int base = 0; base < n; base += 1024) {
        int idx = base + t;
        int x = (idx < n) ? h[idx] : 0;
        int inc = x;
#pragma unroll
        for (int o = 1; o < 32; o <<= 1) {
            int y = __shfl_up_sync(0xFFFFFFFFu, inc, o);
            if (lane >= o) inc += y;
        }
        if (lane == 31) wsum[w] = inc;
        __syncthreads();
        if (w == 0) {
            int v = wsum[lane];
            int wi = v;
#pragma unroll
            for (int o = 1; o < 32; o <<= 1) {
                int y = __shfl_up_sync(0xFFFFFFFFu, wi, o);
                if (lane >= o) wi += y;
            }
            wsum[lane] = wi - v;   // exclusive warp offsets
        }
        __syncthreads();
        int excl = carry + wsum[w] + inc - x;
        if (idx < n) { off[idx] = excl; cur[idx] = excl; }
        __syncthreads();
        if (t == 1023) carry += wsum[31] + inc;
        __syncthreads();
    }
    if (t == 0) off[n] = carry;
}

// ---------------------------------------------------------------------------
// K_reorder: fill both member lists (order within a segment is irrelevant)
// ---------------------------------------------------------------------------
__global__ __launch_bounds__(256) void k_reorder(
    const int* __restrict__ vertex, const int* __restrict__ edges, int n)
{
    int stride = gridDim.x * blockDim.x;
    for (int i = blockIdx.x * blockDim.x + threadIdx.x; i < n; i += stride) {
        int v = vertex[i];
        int e = edges[i];
        int pe = atomicAdd(&g_cur_e[e], 1);
        g_mem_e[pe] = v;
        int pv = atomicAdd(&g_cur_v[v], 1);
        g_mem_v[pv] = e;
    }
}

// ---------------------------------------------------------------------------
// K1: X0 = X @ Ww[0]^T + Wb[0]  -> out (read back by k_agg_v)
// ---------------------------------------------------------------------------
__global__ __launch_bounds__(256) void k_x0(
    const float* __restrict__ X, const float* __restrict__ Ww,
    const float* __restrict__ Wb, float* __restrict__ out, int n_rows)
{
    __shared__ float WsT[64 * 64];    // WsT[i*64+o] = W[o][i]
    __shared__ float Xs [64 * 68];
    int tid = threadIdx.x;
    for (int k = tid; k < 4096; k += 256) {
        int o = k >> 6, i = k & 63;
        WsT[i * 64 + o] = Ww[o * 64 + i];
    }
    int row0 = blockIdx.x * 64;
    for (int k = tid; k < 1024; k += 256) {
        int r = k >> 4, j = k & 15;
        int row = row0 + r;
        float4 v = make_float4(0.f, 0.f, 0.f, 0.f);
        if (row < n_rows) v = ((const float4*)X)[(size_t)row * 16 + j];
        ((float4*)(Xs + r * 68))[j] = v;
    }
    __syncthreads();

    int r = tid >> 2, cg = tid & 3;
    int row = row0 + r;
    float acc[16];
#pragma unroll
    for (int q = 0; q < 16; q++) acc[q] = 0.f;
    const float* xr = Xs + r * 68;
#pragma unroll 8
    for (int i = 0; i < 64; i++) {
        float xv = xr[i];
        const float4* wr = (const float4*)(WsT + i * 64 + cg * 16);
#pragma unroll
        for (int q = 0; q < 4; q++) {
            float4 w = wr[q];
            acc[q * 4 + 0] += xv * w.x;
            acc[q * 4 + 1] += xv * w.y;
            acc[q * 4 + 2] += xv * w.z;
            acc[q * 4 + 3] += xv * w.w;
        }
    }
    if (row < n_rows) {
#pragma unroll
        for (int q = 0; q < 4; q++) {
            int c = cg * 16 + q * 4;
            float4 o4;
            o4.x = acc[q * 4 + 0] + Wb[c + 0];
            o4.y = acc[q * 4 + 1] + Wb[c + 1];
            o4.z = acc[q * 4 + 2] + Wb[c + 2];
            o4.w = acc[q * 4 + 3] + Wb[c + 3];
            ((float4*)(out + (size_t)row * 64))[cg * 4 + q] = o4;
        }
    }
}

// ---------------------------------------------------------------------------
// K_agg_e: per-edge reduce  A[e] = sum_{v in members(e)} degV[t_e][v] * X[v]
//          also g_sd[e] = sum degV. 16 lanes per edge, register accumulation.
// ---------------------------------------------------------------------------
__global__ __launch_bounds__(256) void k_agg_e(
    const float* __restrict__ X, const float* __restrict__ degV)
{
    int e = (blockIdx.x * blockDim.x + threadIdx.x) >> 4;   // grid sized exactly
    int l = threadIdx.x & 15;
    int t = e / 10000;
    const float* degT = degV + t * NNODES;
    int s  = g_off_e[e];
    int en = g_off_e[e + 1];
    float4 acc = make_float4(0.f, 0.f, 0.f, 0.f);
    float  sd  = 0.f;
    int i = s;
    for (; i + 4 <= en; i += 4) {
        int v0 = g_mem_e[i], v1 = g_mem_e[i + 1], v2 = g_mem_e[i + 2], v3 = g_mem_e[i + 3];
        float d0 = degT[v0], d1 = degT[v1], d2 = degT[v2], d3 = degT[v3];
        float4 x0 = ((const float4*)X)[(size_t)v0 * 16 + l];
        float4 x1 = ((const float4*)X)[(size_t)v1 * 16 + l];
        float4 x2 = ((const float4*)X)[(size_t)v2 * 16 + l];
        float4 x3 = ((const float4*)X)[(size_t)v3 * 16 + l];
        acc.x += d0 * x0.x + d1 * x1.x + d2 * x2.x + d3 * x3.x;
        acc.y += d0 * x0.y + d1 * x1.y + d2 * x2.y + d3 * x3.y;
        acc.z += d0 * x0.z + d1 * x1.z + d2 * x2.z + d3 * x3.z;
        acc.w += d0 * x0.w + d1 * x1.w + d2 * x2.w + d3 * x3.w;
        sd += d0 + d1 + d2 + d3;
    }
    for (; i < en; i++) {
        int v = g_mem_e[i];
        float d = degT[v];
        float4 x = ((const float4*)X)[(size_t)v * 16 + l];
        acc.x += d * x.x; acc.y += d * x.y; acc.z += d * x.z; acc.w += d * x.w;
        sd += d;
    }
    ((float4*)g_A)[(size_t)e * 16 + l] = acc;
    if (l == 0) g_sd[e] = sd;
}

// ---------------------------------------------------------------------------
// K_edge: Xe[e] = (W_{t+1} @ A[e] + b_{t+1}*sd[e]) / max(cnt[e],1)
// ---------------------------------------------------------------------------
__global__ __launch_bounds__(256) void k_edge(
    const float* __restrict__ Ww, const float* __restrict__ Wb)
{
    const int CHUNKS = 157;                 // ceil(10000/64)
    int t     = blockIdx.x / CHUNKS;
    int chunk = blockIdx.x % CHUNKS;
    int base  = t * 10000 + chunk * 64;
    int limit = (t + 1) * 10000;

    __shared__ float WsT[64 * 64];
    __shared__ float As [64 * 68];
    const float* W = Ww + (size_t)(t + 1) * 4096;
    const float* b = Wb + (size_t)(t + 1) * 64;
    int tid = threadIdx.x;
    for (int k = tid; k < 4096; k += 256) {
        int o = k >> 6, i = k & 63;
        WsT[i * 64 + o] = W[o * 64 + i];
    }
    for (int k = tid; k < 1024; k += 256) {
        int r = k >> 4, j = k & 15;
        int e = base + r;
        float4 v = make_float4(0.f, 0.f, 0.f, 0.f);
        if (e < limit) v = ((const float4*)(g_A))[(size_t)e * 16 + j];
        ((float4*)(As + r * 68))[j] = v;
    }
    __syncthreads();

    int r = tid >> 2, cg = tid & 3;
    int e = base + r;
    float acc[16];
#pragma unroll
    for (int q = 0; q < 16; q++) acc[q] = 0.f;
    const float* ar = As + r * 68;
#pragma unroll 8
    for (int i = 0; i < 64; i++) {
        float av = ar[i];
        const float4* wr = (const float4*)(WsT + i * 64 + cg * 16);
#pragma unroll
        for (int q = 0; q < 4; q++) {
            float4 w = wr[q];
            acc[q * 4 + 0] += av * w.x;
            acc[q * 4 + 1] += av * w.y;
            acc[q * 4 + 2] += av * w.z;
            acc[q * 4 + 3] += av * w.w;
        }
    }
    if (e < limit) {
        float sd  = g_sd[e];
        int   cnt = g_off_e[e + 1] - g_off_e[e];
        float inv = 1.0f / fmaxf((float)cnt, 1.0f);
#pragma unroll
        for (int q = 0; q < 4; q++) {
            int col = cg * 16 + q * 4;
            float4 o4;
            o4.x = (acc[q * 4 + 0] + b[col + 0] * sd) * inv;
            o4.y = (acc[q * 4 + 1] + b[col + 1] * sd) * inv;
            o4.z = (acc[q * 4 + 2] + b[col + 2] * sd) * inv;
            o4.w = (acc[q * 4 + 3] + b[col + 3] * sd) * inv;
            ((float4*)(g_Xe + (size_t)e * 64))[cg * 4 + q] = o4;
        }
    }
}

// ---------------------------------------------------------------------------
// K_agg_v: out[v] = leaky_relu(l2norm(X0[v] + sum_{e in members(v)} Xe[e]))
// 16 lanes per vertex; fused epilogue.
// ---------------------------------------------------------------------------
__global__ __launch_bounds__(256) void k_agg_v(float* __restrict__ out)
{
    int v = (blockIdx.x * blockDim.x + threadIdx.x) >> 4;   // grid sized exactly
    int l = threadIdx.x & 15;
    int s  = g_off_v[v];
    int en = g_off_v[v + 1];
    float4 acc = ((const float4*)out)[(size_t)v * 16 + l];  // X0
    int i = s;
    for (; i + 4 <= en; i += 4) {
        int e0 = g_mem_v[i], e1 = g_mem_v[i + 1], e2 = g_mem_v[i + 2], e3 = g_mem_v[i + 3];
        float4 a0 = ((const float4*)g_Xe)[(size_t)e0 * 16 + l];
        float4 a1 = ((const float4*)g_Xe)[(size_t)e1 * 16 + l];
        float4 a2 = ((const float4*)g_Xe)[(size_t)e2 * 16 + l];
        float4 a3 = ((const float4*)g_Xe)[(size_t)e3 * 16 + l];
        acc.x += a0.x + a1.x + a2.x + a3.x;
        acc.y += a0.y + a1.y + a2.y + a3.y;
        acc.z += a0.z + a1.z + a2.z + a3.z;
        acc.w += a0.w + a1.w + a2.w + a3.w;
    }
    for (; i < en; i++) {
        int e = g_mem_v[i];
        float4 a = ((const float4*)g_Xe)[(size_t)e * 16 + l];
        acc.x += a.x; acc.y += a.y; acc.z += a.z; acc.w += a.w;
    }
    // fused L2-norm + leaky relu over the 16-lane group
    float ss = acc.x * acc.x + acc.y * acc.y + acc.z * acc.z + acc.w * acc.w;
#pragma unroll
    for (int o = 8; o > 0; o >>= 1)
        ss += __shfl_xor_sync(0xFFFFFFFFu, ss, o);
    float rn = sqrtf(ss);
    float sc = (rn == 0.0f) ? 0.0f : 1.0f / rn;
    acc.x *= sc; acc.y *= sc; acc.z *= sc; acc.w *= sc;
    acc.x = (acc.x >= 0.f) ? acc.x : NEG_SLOPE * acc.x;
    acc.y = (acc.y >= 0.f) ? acc.y : NEG_SLOPE * acc.y;
    acc.z = (acc.z >= 0.f) ? acc.z : NEG_SLOPE * acc.z;
    acc.w = (acc.w >= 0.f) ? acc.w : NEG_SLOPE * acc.w;
    ((float4*)out)[(size_t)v * 16 + l] = acc;
}

// ---------------------------------------------------------------------------
extern "C" void kernel_launch(void* const* d_in, const int* in_sizes, int n_in,
                              void* d_out, int out_size)
{
    const float* X      = (const float*)d_in[0];   // [100000, 64] f32
    const float* degV   = (const float*)d_in[1];   // [3, 100000, 1] f32
    const float* Ww     = (const float*)d_in[2];   // [4, 64, 64] f32
    const float* Wb     = (const float*)d_in[3];   // [4, 64] f32
    const int*   vertex = (const int*)d_in[4];     // [1.6M] int32
    const int*   edges  = (const int*)d_in[5];     // [1.6M] int32
    float*       out    = (float*)d_out;           // [100000, 64] f32

    int n_pairs = in_sizes[4];

    k_init   <<<(NNODES + 255) / 256, 256>>>();
    k_hist   <<<1184, 256>>>(vertex, edges, n_pairs);
    k_scan   <<<2, 1024>>>();
    k_reorder<<<1184, 256>>>(vertex, edges, n_pairs);
    k_x0     <<<(NNODES + 63) / 64, 256>>>(X, Ww, Wb, out, NNODES);
    k_agg_e  <<<(NEDGES * 16) / 256, 256>>>(X, degV);
    k_edge   <<<3 * 157, 256>>>(Ww, Wb);
    k_agg_v  <<<(NNODES * 16) / 256, 256>>>(out);
}